// round 3
// baseline (speedup 1.0000x reference)
#include <cuda_runtime.h>
#include <math.h>

constexpr int Nn  = 50000;
constexpr int Ee  = 800000;
constexpr int CIN = 16;
constexpr int CO  = 64;

typedef unsigned long long ull;

// ---------------- device scratch ---------------------------------------------
__device__ int   g_is64;
__device__ float g_deg[Nn];
__device__ float g_dinv[Nn];
__device__ int   g_cnt[Nn];
__device__ int   g_rowptr[Nn + 1];
__device__ int   g_fill[Nn];
__device__ int   g_csrc[Ee];
__device__ float g_cw[Ee];

__device__ float g_tx1[Nn * CIN];
__device__ float g_tx2[Nn * CIN];
__device__ float g_th1[Nn * CO];
__device__ float g_th2[Nn * CO];
__device__ float g_hr [Nn * CO];
__device__ float g_tr1[Nn * CO];
__device__ float g_tr2[Nn * CO];
__device__ float g_z  [Nn * CO];

// ---------------- small helpers ----------------------------------------------
__device__ __forceinline__ ull pack2(float lo, float hi) {
    ull r; asm("mov.b64 %0, {%1, %2};" : "=l"(r) : "f"(lo), "f"(hi)); return r;
}
__device__ __forceinline__ float2 unpack2(ull v) {
    float2 f; asm("mov.b64 {%0, %1}, %2;" : "=f"(f.x), "=f"(f.y) : "l"(v)); return f;
}
__device__ __forceinline__ void ffma2(ull& d, ull a, ull b) {
    asm("fma.rn.f32x2 %0, %1, %2, %0;" : "+l"(d) : "l"(a), "l"(b));
}
__device__ __forceinline__ float tanh_ap(float v) {
    float r; asm("tanh.approx.f32 %0, %1;" : "=f"(r) : "f"(v)); return r;
}
__device__ __forceinline__ float sigmoid_ap(float v) {
    return fmaf(tanh_ap(0.5f * v), 0.5f, 0.5f);
}

__device__ __forceinline__ void load_edge(const void* ei, int e, int& s, int& d) {
    if (g_is64) {
        const long long* p = (const long long*)ei;
        s = (int)p[e]; d = (int)p[Ee + e];
    } else {
        const int* p = (const int*)ei;
        s = p[e]; d = p[Ee + e];
    }
}

// ---------------- preprocessing ----------------------------------------------
__global__ void k_init(const unsigned* __restrict__ ei_raw) {
    int i = blockIdx.x * blockDim.x + threadIdx.x;
    if (i < Nn) { g_deg[i] = 0.f; g_cnt[i] = 0; }
    if (blockIdx.x == 0) {
        if (threadIdx.x == 0) g_is64 = 1;
        __syncthreads();
        if (threadIdx.x < 256) {
            if (ei_raw[2 * threadIdx.x + 1] != 0u) atomicExch(&g_is64, 0);
        }
    }
}

__global__ void k_degcnt(const void* __restrict__ ei, const float* __restrict__ ew) {
    int e = blockIdx.x * blockDim.x + threadIdx.x;
    if (e >= Ee) return;
    int s, d; load_edge(ei, e, s, d);
    float w = ew[e];
    if (s != d) atomicAdd(&g_deg[s], w);
    atomicAdd(&g_cnt[d], 1);
}

__global__ void k_dinv() {
    int i = blockIdx.x * blockDim.x + threadIdx.x;
    if (i >= Nn) return;
    float d = g_deg[i];
    g_dinv[i] = (d > 0.f) ? rsqrtf(d) : 0.f;
}

// chunk-per-thread scan: 1024 threads, 49 elems each
__global__ void k_scan() {
    __shared__ int sm[1024];
    int t = threadIdx.x;
    const int CH = (Nn + 1023) / 1024;
    int b = t * CH, e = min(b + CH, Nn);
    int s = 0;
    for (int i = b; i < e; i++) s += g_cnt[i];
    sm[t] = s;
    __syncthreads();
    for (int off = 1; off < 1024; off <<= 1) {
        int v = (t >= off) ? sm[t - off] : 0;
        __syncthreads();
        sm[t] += v;
        __syncthreads();
    }
    int run = (t > 0) ? sm[t - 1] : 0;
    if (t == 0) g_rowptr[0] = 0;
    for (int i = b; i < e; i++) {
        int v = g_cnt[i];
        g_fill[i] = run;
        run += v;
        g_rowptr[i + 1] = run;
    }
}

__global__ void k_csr(const void* __restrict__ ei, const float* __restrict__ ew) {
    int e = blockIdx.x * blockDim.x + threadIdx.x;
    if (e >= Ee) return;
    int s, d; load_edge(ei, e, s, d);
    float w  = ew[e];
    float wz = (s == d) ? 0.f : w;
    float nw = -g_dinv[s] * wz * g_dinv[d];
    int pos = atomicAdd(&g_fill[d], 1);
    g_csrc[pos] = s;
    g_cw[pos]   = nw;
}

// ---------------- propagation (pull, CSR-by-dst) ------------------------------
// fused x(16ch) + h(64ch) hop: warp per dst node, shared edge stream
__global__ void k_prop_xh1(const float* __restrict__ x, const float* __restrict__ h0) {
    int w = (blockIdx.x * blockDim.x + threadIdx.x) >> 5;
    if (w >= Nn) return;
    int lane = threadIdx.x & 31, cx = lane & 15;
    int beg = g_rowptr[w], end = g_rowptr[w + 1];
    float a0 = 0.f, a1 = 0.f, ax = 0.f;
    int e = beg;
    for (; e + 1 < end; e += 2) {
        int   s0 = g_csrc[e], s1 = g_csrc[e + 1];
        float w0 = g_cw[e],   w1 = g_cw[e + 1];
        a0 = fmaf(w0, h0[s0 * 64 + lane],      fmaf(w1, h0[s1 * 64 + lane],      a0));
        a1 = fmaf(w0, h0[s0 * 64 + 32 + lane], fmaf(w1, h0[s1 * 64 + 32 + lane], a1));
        ax = fmaf(w0, x [s0 * 16 + cx],        fmaf(w1, x [s1 * 16 + cx],        ax));
    }
    if (e < end) {
        int s = g_csrc[e]; float ww = g_cw[e];
        a0 = fmaf(ww, h0[s * 64 + lane], a0);
        a1 = fmaf(ww, h0[s * 64 + 32 + lane], a1);
        ax = fmaf(ww, x[s * 16 + cx], ax);
    }
    g_th1[w * 64 + lane]      = a0;
    g_th1[w * 64 + 32 + lane] = a1;
    if (lane < 16) g_tx1[w * 16 + lane] = ax;
}

__global__ void k_prop_xh2(const float* __restrict__ x, const float* __restrict__ h0) {
    int w = (blockIdx.x * blockDim.x + threadIdx.x) >> 5;
    if (w >= Nn) return;
    int lane = threadIdx.x & 31, cx = lane & 15;
    int beg = g_rowptr[w], end = g_rowptr[w + 1];
    float a0 = 0.f, a1 = 0.f, ax = 0.f;
    int e = beg;
    for (; e + 1 < end; e += 2) {
        int   s0 = g_csrc[e], s1 = g_csrc[e + 1];
        float w0 = g_cw[e],   w1 = g_cw[e + 1];
        a0 = fmaf(w0, g_th1[s0 * 64 + lane],      fmaf(w1, g_th1[s1 * 64 + lane],      a0));
        a1 = fmaf(w0, g_th1[s0 * 64 + 32 + lane], fmaf(w1, g_th1[s1 * 64 + 32 + lane], a1));
        ax = fmaf(w0, g_tx1[s0 * 16 + cx],        fmaf(w1, g_tx1[s1 * 16 + cx],        ax));
    }
    if (e < end) {
        int s = g_csrc[e]; float ww = g_cw[e];
        a0 = fmaf(ww, g_th1[s * 64 + lane], a0);
        a1 = fmaf(ww, g_th1[s * 64 + 32 + lane], a1);
        ax = fmaf(ww, g_tx1[s * 16 + cx], ax);
    }
    g_th2[w * 64 + lane]      = 2.f * a0 - h0[w * 64 + lane];
    g_th2[w * 64 + 32 + lane] = 2.f * a1 - h0[w * 64 + 32 + lane];
    if (lane < 16) g_tx2[w * 16 + lane] = 2.f * ax - x[w * 16 + lane];
}

__device__ __forceinline__ void prop64_core(const float* __restrict__ vin,
                                            const float* __restrict__ sub,
                                            float* __restrict__ vout,
                                            bool fuse) {
    int w = (blockIdx.x * blockDim.x + threadIdx.x) >> 5;
    if (w >= Nn) return;
    int lane = threadIdx.x & 31;
    int beg = g_rowptr[w], end = g_rowptr[w + 1];
    float a0 = 0.f, a1 = 0.f;
    int e = beg;
    for (; e + 1 < end; e += 2) {
        int   s0 = g_csrc[e], s1 = g_csrc[e + 1];
        float w0 = g_cw[e],   w1 = g_cw[e + 1];
        a0 = fmaf(w0, vin[s0 * 64 + lane],      fmaf(w1, vin[s1 * 64 + lane],      a0));
        a1 = fmaf(w0, vin[s0 * 64 + 32 + lane], fmaf(w1, vin[s1 * 64 + 32 + lane], a1));
    }
    if (e < end) {
        int s = g_csrc[e]; float ww = g_cw[e];
        a0 = fmaf(ww, vin[s * 64 + lane], a0);
        a1 = fmaf(ww, vin[s * 64 + 32 + lane], a1);
    }
    if (fuse) {
        a0 = 2.f * a0 - sub[w * 64 + lane];
        a1 = 2.f * a1 - sub[w * 64 + 32 + lane];
    }
    vout[w * 64 + lane]      = a0;
    vout[w * 64 + 32 + lane] = a1;
}

__global__ void k_prop_r1() { prop64_core(g_hr,  nullptr, g_tr1, false); }
__global__ void k_prop_r2() { prop64_core(g_tr1, g_hr,    g_tr2, true ); }

// ---------------- GEMM zr: [32 rows] x (192 h-K + 48 x-K) -> z, hr ------------
// 128 threads: g = tid>>6 (gate z|r), co = tid&63. f32x2 packed row-pairs.
constexpr int GR = 32;

__global__ void k_gemm_zr(const float* __restrict__ x,  const float* __restrict__ h0,
                          const float* __restrict__ Wx, const float* __restrict__ Wh,
                          const float* __restrict__ bx, const float* __restrict__ bh) {
    __shared__ __align__(16) float sAh[192][34];
    __shared__ __align__(16) float sAx[48][34];
    int tid  = threadIdx.x;
    int row0 = blockIdx.x * GR;
    for (int i = tid; i < GR * 192; i += 128) {
        int r = i / 192, kk = i - r * 192;
        int row = min(row0 + r, Nn - 1);
        int c = kk & 63, seg = kk >> 6;
        float v = (seg == 0) ? h0[row * 64 + c]
                : (seg == 1) ? g_th1[row * 64 + c]
                             : g_th2[row * 64 + c];
        sAh[kk][r] = v;
    }
    for (int i = tid; i < GR * 48; i += 128) {
        int r = i / 48, kk = i - r * 48;
        int row = min(row0 + r, Nn - 1);
        int c = kk & 15, seg = kk >> 4;
        float v = (seg == 0) ? x[row * 16 + c]
                : (seg == 1) ? g_tx1[row * 16 + c]
                             : g_tx2[row * 16 + c];
        sAx[kk][r] = v;
    }
    __syncthreads();

    int g = tid >> 6, co = tid & 63;
    ull acc[16];
#pragma unroll
    for (int r = 0; r < 16; r++) acc[r] = 0ull;

    const float* Wgh = Wh + (g * 192) * 64 + co;
    for (int kk = 0; kk < 192; kk++) {
        float w = Wgh[kk * 64];
        ull w2 = pack2(w, w);
        const ull* ap = (const ull*)sAh[kk];
#pragma unroll
        for (int r = 0; r < 16; r++) ffma2(acc[r], ap[r], w2);
    }
    const float* Wgx = Wx + (g * 48) * 64 + co;
    for (int kk = 0; kk < 48; kk++) {
        float w = Wgx[kk * 64];
        ull w2 = pack2(w, w);
        const ull* ap = (const ull*)sAx[kk];
#pragma unroll
        for (int r = 0; r < 16; r++) ffma2(acc[r], ap[r], w2);
    }

    float b = bh[g * 64 + co] + bx[g * 64 + co];
#pragma unroll
    for (int r = 0; r < 16; r++) {
        float2 v = unpack2(acc[r]);
        int rowa = row0 + 2 * r, rowb = rowa + 1;
        float sa = sigmoid_ap(v.x + b);
        float sb = sigmoid_ap(v.y + b);
        if (g == 0) {
            if (rowa < Nn) g_z[rowa * 64 + co] = sa;
            if (rowb < Nn) g_z[rowb * 64 + co] = sb;
        } else {
            if (rowa < Nn) g_hr[rowa * 64 + co] = sa * h0[rowa * 64 + co];
            if (rowb < Nn) g_hr[rowb * 64 + co] = sb * h0[rowb * 64 + co];
        }
    }
}

// ---------------- GEMM til: -> htil, h (blend), + fused y = relu(h)@Wlin ------
// 128 threads: co = tid&63, rh = tid>>6 (row half: 16 rows each -> 8 pairs)
__global__ void k_gemm_til(const float* __restrict__ x,  const float* __restrict__ h0,
                           const float* __restrict__ Wx, const float* __restrict__ Wh,
                           const float* __restrict__ bx, const float* __restrict__ bh,
                           const float* __restrict__ Wlin, const float* __restrict__ blin,
                           float* __restrict__ hout, float* __restrict__ yout) {
    __shared__ __align__(16) float sAh[192][34];
    __shared__ __align__(16) float sAx[48][34];
    __shared__ float sH[GR][65];
    int tid  = threadIdx.x;
    int row0 = blockIdx.x * GR;
    for (int i = tid; i < GR * 192; i += 128) {
        int r = i / 192, kk = i - r * 192;
        int row = min(row0 + r, Nn - 1);
        int c = kk & 63, seg = kk >> 6;
        float v = (seg == 0) ? g_hr[row * 64 + c]
                : (seg == 1) ? g_tr1[row * 64 + c]
                             : g_tr2[row * 64 + c];
        sAh[kk][r] = v;
    }
    for (int i = tid; i < GR * 48; i += 128) {
        int r = i / 48, kk = i - r * 48;
        int row = min(row0 + r, Nn - 1);
        int c = kk & 15, seg = kk >> 4;
        float v = (seg == 0) ? x[row * 16 + c]
                : (seg == 1) ? g_tx1[row * 16 + c]
                             : g_tx2[row * 16 + c];
        sAx[kk][r] = v;
    }
    __syncthreads();

    int co = tid & 63, rh = tid >> 6;
    ull acc[8];
#pragma unroll
    for (int r = 0; r < 8; r++) acc[r] = 0ull;

    const float* Wgh = Wh + (2 * 192) * 64 + co;
    for (int kk = 0; kk < 192; kk++) {
        float w = Wgh[kk * 64];
        ull w2 = pack2(w, w);
        const ull* ap = (const ull*)sAh[kk] + rh * 8;
#pragma unroll
        for (int r = 0; r < 8; r++) ffma2(acc[r], ap[r], w2);
    }
    const float* Wgx = Wx + (2 * 48) * 64 + co;
    for (int kk = 0; kk < 48; kk++) {
        float w = Wgx[kk * 64];
        ull w2 = pack2(w, w);
        const ull* ap = (const ull*)sAx[kk] + rh * 8;
#pragma unroll
        for (int r = 0; r < 8; r++) ffma2(acc[r], ap[r], w2);
    }

    float b = bh[128 + co] + bx[128 + co];
#pragma unroll
    for (int r = 0; r < 8; r++) {
        float2 v = unpack2(acc[r]);
        int lr = rh * 16 + 2 * r;
#pragma unroll
        for (int hh = 0; hh < 2; hh++) {
            float pre = ((hh == 0) ? v.x : v.y) + b;
            int row = row0 + lr + hh;
            float ht = tanh_ap(pre);
            float z, hv = 0.f;
            if (row < Nn) {
                z  = g_z[row * 64 + co];
                hv = z * h0[row * 64 + co] + (1.0f - z) * ht;
                hout[row * 64 + co] = hv;
            }
            sH[lr + hh][co] = fmaxf(hv, 0.f);
        }
    }
    __syncthreads();

    // y = relu(h) @ Wlin + blin  (32 rows x 7 outputs per CTA)
    for (int i = tid; i < GR * 7; i += 128) {
        int r = i / 7, j = i - r * 7;
        int row = row0 + r;
        if (row >= Nn) continue;
        float s = blin[j];
#pragma unroll 16
        for (int c = 0; c < 64; c++) s = fmaf(sH[r][c], Wlin[c * 7 + j], s);
        yout[row * 7 + j] = s;
    }
}

// ---------------- launch ------------------------------------------------------
extern "C" void kernel_launch(void* const* d_in, const int* in_sizes, int n_in,
                              void* d_out, int out_size) {
    const float* x    = (const float*)d_in[0];
    const void*  ei   = d_in[1];
    const float* ew   = (const float*)d_in[2];
    const float* h0   = (const float*)d_in[3];
    const float* Wx   = (const float*)d_in[4];
    const float* Wh   = (const float*)d_in[5];
    const float* bx   = (const float*)d_in[6];
    const float* bh   = (const float*)d_in[7];
    const float* Wlin = (const float*)d_in[8];
    const float* blin = (const float*)d_in[9];
    float* out  = (float*)d_out;
    float* hout = out;
    float* yout = out + (size_t)Nn * 64;

    const int TB = 256;
    const int gN = (Nn + TB - 1) / TB;
    const int gE = (Ee + TB - 1) / TB;
    const int gW = (Nn * 32 + TB - 1) / TB;   // warp-per-node grids
    const int gG = (Nn + GR - 1) / GR;        // GEMM grids

    k_init  <<<gN, TB>>>((const unsigned*)ei);
    k_degcnt<<<gE, TB>>>(ei, ew);
    k_dinv  <<<gN, TB>>>();
    k_scan  <<<1, 1024>>>();
    k_csr   <<<gE, TB>>>(ei, ew);

    k_prop_xh1<<<gW, TB>>>(x, h0);
    k_prop_xh2<<<gW, TB>>>(x, h0);
    k_gemm_zr <<<gG, 128>>>(x, h0, Wx, Wh, bx, bh);

    k_prop_r1 <<<gW, TB>>>();
    k_prop_r2 <<<gW, TB>>>();
    k_gemm_til<<<gG, 128>>>(x, h0, Wx, Wh, bx, bh, Wlin, blin, hout, yout);
}

// round 4
// speedup vs baseline: 1.1729x; 1.1729x over previous
#include <cuda_runtime.h>
#include <math.h>

constexpr int Nn  = 50000;
constexpr int Ee  = 800000;
constexpr int CIN = 16;
constexpr int CO  = 64;
constexpr int SBK = 256;                       // scan block size
constexpr int NBLK = (Nn + SBK - 1) / SBK;     // 196 scan blocks

typedef unsigned long long ull;

// ---------------- device scratch ---------------------------------------------
__device__ int   g_is64;
__device__ float g_deg[Nn];
__device__ float g_dinv[Nn];
__device__ int   g_cnt[Nn];
__device__ int   g_rowptr[Nn + 1];
__device__ int   g_fill[Nn];
__device__ int   g_bsum[NBLK];
__device__ int   g_boff[NBLK];
__device__ int   g_csrc[Ee];
__device__ float g_cw[Ee];

__device__ float g_tx1[Nn * CIN];
__device__ float g_tx2[Nn * CIN];
__device__ float g_th1[Nn * CO];
__device__ float g_th2[Nn * CO];
__device__ float g_hr [Nn * CO];
__device__ float g_tr1[Nn * CO];
__device__ float g_tr2[Nn * CO];
__device__ float g_z  [Nn * CO];

// ---------------- small helpers ----------------------------------------------
__device__ __forceinline__ ull pack2(float lo, float hi) {
    ull r; asm("mov.b64 %0, {%1, %2};" : "=l"(r) : "f"(lo), "f"(hi)); return r;
}
__device__ __forceinline__ float2 unpack2(ull v) {
    float2 f; asm("mov.b64 {%0, %1}, %2;" : "=f"(f.x), "=f"(f.y) : "l"(v)); return f;
}
__device__ __forceinline__ void ffma2(ull& d, ull a, ull b) {
    asm("fma.rn.f32x2 %0, %1, %2, %0;" : "+l"(d) : "l"(a), "l"(b));
}
__device__ __forceinline__ float tanh_ap(float v) {
    float r; asm("tanh.approx.f32 %0, %1;" : "=f"(r) : "f"(v)); return r;
}
__device__ __forceinline__ float sigmoid_ap(float v) {
    return fmaf(tanh_ap(0.5f * v), 0.5f, 0.5f);
}

__device__ __forceinline__ void load_edge(const void* ei, int e, int& s, int& d) {
    if (g_is64) {
        const long long* p = (const long long*)ei;
        s = (int)p[e]; d = (int)p[Ee + e];
    } else {
        const int* p = (const int*)ei;
        s = p[e]; d = p[Ee + e];
    }
}

// ---------------- preprocessing ----------------------------------------------
__global__ void k_init(const unsigned* __restrict__ ei_raw) {
    int i = blockIdx.x * blockDim.x + threadIdx.x;
    if (i < Nn) { g_deg[i] = 0.f; g_cnt[i] = 0; }
    if (blockIdx.x == 0) {
        if (threadIdx.x == 0) g_is64 = 1;
        __syncthreads();
        if (threadIdx.x < 256) {
            if (ei_raw[2 * threadIdx.x + 1] != 0u) atomicExch(&g_is64, 0);
        }
    }
}

__global__ void k_degcnt(const void* __restrict__ ei, const float* __restrict__ ew) {
    int e = blockIdx.x * blockDim.x + threadIdx.x;
    if (e >= Ee) return;
    int s, d; load_edge(ei, e, s, d);
    float w = ew[e];
    if (s != d) atomicAdd(&g_deg[s], w);
    atomicAdd(&g_cnt[d], 1);
}

// phase 1: intra-block inclusive scan of cnt (partial, no offset) + dinv fused
__global__ void k_scan1() {
    __shared__ int sm[SBK];
    int b = blockIdx.x, t = threadIdx.x;
    int i = b * SBK + t;
    int v = (i < Nn) ? g_cnt[i] : 0;
    sm[t] = v;
    __syncthreads();
#pragma unroll
    for (int off = 1; off < SBK; off <<= 1) {
        int u = (t >= off) ? sm[t - off] : 0;
        __syncthreads();
        sm[t] += u;
        __syncthreads();
    }
    if (i < Nn) {
        g_rowptr[i + 1] = sm[t];
        float dg = g_deg[i];
        g_dinv[i] = (dg > 0.f) ? rsqrtf(dg) : 0.f;
    }
    if (t == SBK - 1) g_bsum[b] = sm[t];
}

// phase 2: single block scans the block sums -> exclusive offsets
__global__ void k_scan2() {
    __shared__ int sm[SBK];
    int t = threadIdx.x;
    int v = (t < NBLK) ? g_bsum[t] : 0;
    sm[t] = v;
    __syncthreads();
#pragma unroll
    for (int off = 1; off < SBK; off <<= 1) {
        int u = (t >= off) ? sm[t - off] : 0;
        __syncthreads();
        sm[t] += u;
        __syncthreads();
    }
    if (t < NBLK) g_boff[t] = sm[t] - v;
}

// phase 3: add block offsets, finalize rowptr + fill
__global__ void k_scan3() {
    int b = blockIdx.x, t = threadIdx.x;
    int i = b * SBK + t;
    if (i >= Nn) return;
    int incl = g_rowptr[i + 1] + g_boff[b];
    g_rowptr[i + 1] = incl;
    g_fill[i] = incl - g_cnt[i];
    if (i == 0) g_rowptr[0] = 0;
}

__global__ void k_csr(const void* __restrict__ ei, const float* __restrict__ ew) {
    int e = blockIdx.x * blockDim.x + threadIdx.x;
    if (e >= Ee) return;
    int s, d; load_edge(ei, e, s, d);
    float w  = ew[e];
    float wz = (s == d) ? 0.f : w;
    float nw = -g_dinv[s] * wz * g_dinv[d];
    int pos = atomicAdd(&g_fill[d], 1);
    g_csrc[pos] = s;
    g_cw[pos]   = nw;
}

// ---------------- propagation (pull, CSR-by-dst) ------------------------------
__global__ void k_prop_xh1(const float* __restrict__ x, const float* __restrict__ h0) {
    int w = (blockIdx.x * blockDim.x + threadIdx.x) >> 5;
    if (w >= Nn) return;
    int lane = threadIdx.x & 31, cx = lane & 15;
    int beg = g_rowptr[w], end = g_rowptr[w + 1];
    float a0 = 0.f, a1 = 0.f, ax = 0.f;
    int e = beg;
    for (; e + 1 < end; e += 2) {
        int   s0 = g_csrc[e], s1 = g_csrc[e + 1];
        float w0 = g_cw[e],   w1 = g_cw[e + 1];
        a0 = fmaf(w0, h0[s0 * 64 + lane],      fmaf(w1, h0[s1 * 64 + lane],      a0));
        a1 = fmaf(w0, h0[s0 * 64 + 32 + lane], fmaf(w1, h0[s1 * 64 + 32 + lane], a1));
        ax = fmaf(w0, x [s0 * 16 + cx],        fmaf(w1, x [s1 * 16 + cx],        ax));
    }
    if (e < end) {
        int s = g_csrc[e]; float ww = g_cw[e];
        a0 = fmaf(ww, h0[s * 64 + lane], a0);
        a1 = fmaf(ww, h0[s * 64 + 32 + lane], a1);
        ax = fmaf(ww, x[s * 16 + cx], ax);
    }
    g_th1[w * 64 + lane]      = a0;
    g_th1[w * 64 + 32 + lane] = a1;
    if (lane < 16) g_tx1[w * 16 + lane] = ax;
}

__global__ void k_prop_xh2(const float* __restrict__ x, const float* __restrict__ h0) {
    int w = (blockIdx.x * blockDim.x + threadIdx.x) >> 5;
    if (w >= Nn) return;
    int lane = threadIdx.x & 31, cx = lane & 15;
    int beg = g_rowptr[w], end = g_rowptr[w + 1];
    float a0 = 0.f, a1 = 0.f, ax = 0.f;
    int e = beg;
    for (; e + 1 < end; e += 2) {
        int   s0 = g_csrc[e], s1 = g_csrc[e + 1];
        float w0 = g_cw[e],   w1 = g_cw[e + 1];
        a0 = fmaf(w0, g_th1[s0 * 64 + lane],      fmaf(w1, g_th1[s1 * 64 + lane],      a0));
        a1 = fmaf(w0, g_th1[s0 * 64 + 32 + lane], fmaf(w1, g_th1[s1 * 64 + 32 + lane], a1));
        ax = fmaf(w0, g_tx1[s0 * 16 + cx],        fmaf(w1, g_tx1[s1 * 16 + cx],        ax));
    }
    if (e < end) {
        int s = g_csrc[e]; float ww = g_cw[e];
        a0 = fmaf(ww, g_th1[s * 64 + lane], a0);
        a1 = fmaf(ww, g_th1[s * 64 + 32 + lane], a1);
        ax = fmaf(ww, g_tx1[s * 16 + cx], ax);
    }
    g_th2[w * 64 + lane]      = 2.f * a0 - h0[w * 64 + lane];
    g_th2[w * 64 + 32 + lane] = 2.f * a1 - h0[w * 64 + 32 + lane];
    if (lane < 16) g_tx2[w * 16 + lane] = 2.f * ax - x[w * 16 + lane];
}

__device__ __forceinline__ void prop64_core(const float* __restrict__ vin,
                                            const float* __restrict__ sub,
                                            float* __restrict__ vout,
                                            bool fuse) {
    int w = (blockIdx.x * blockDim.x + threadIdx.x) >> 5;
    if (w >= Nn) return;
    int lane = threadIdx.x & 31;
    int beg = g_rowptr[w], end = g_rowptr[w + 1];
    float a0 = 0.f, a1 = 0.f;
    int e = beg;
    for (; e + 1 < end; e += 2) {
        int   s0 = g_csrc[e], s1 = g_csrc[e + 1];
        float w0 = g_cw[e],   w1 = g_cw[e + 1];
        a0 = fmaf(w0, vin[s0 * 64 + lane],      fmaf(w1, vin[s1 * 64 + lane],      a0));
        a1 = fmaf(w0, vin[s0 * 64 + 32 + lane], fmaf(w1, vin[s1 * 64 + 32 + lane], a1));
    }
    if (e < end) {
        int s = g_csrc[e]; float ww = g_cw[e];
        a0 = fmaf(ww, vin[s * 64 + lane], a0);
        a1 = fmaf(ww, vin[s * 64 + 32 + lane], a1);
    }
    if (fuse) {
        a0 = 2.f * a0 - sub[w * 64 + lane];
        a1 = 2.f * a1 - sub[w * 64 + 32 + lane];
    }
    vout[w * 64 + lane]      = a0;
    vout[w * 64 + 32 + lane] = a1;
}

__global__ void k_prop_r1() { prop64_core(g_hr,  nullptr, g_tr1, false); }
__global__ void k_prop_r2() { prop64_core(g_tr1, g_hr,    g_tr2, true ); }

// ---------------- GEMM zr: [32 rows] x (192 h-K + 48 x-K) -> z, hr ------------
constexpr int GR = 32;

__global__ void k_gemm_zr(const float* __restrict__ x,  const float* __restrict__ h0,
                          const float* __restrict__ Wx, const float* __restrict__ Wh,
                          const float* __restrict__ bx, const float* __restrict__ bh) {
    __shared__ __align__(16) float sAh[192][34];
    __shared__ __align__(16) float sAx[48][34];
    int tid  = threadIdx.x;
    int row0 = blockIdx.x * GR;
    for (int i = tid; i < GR * 192; i += 128) {
        int r = i / 192, kk = i - r * 192;
        int row = min(row0 + r, Nn - 1);
        int c = kk & 63, seg = kk >> 6;
        float v = (seg == 0) ? h0[row * 64 + c]
                : (seg == 1) ? g_th1[row * 64 + c]
                             : g_th2[row * 64 + c];
        sAh[kk][r] = v;
    }
    for (int i = tid; i < GR * 48; i += 128) {
        int r = i / 48, kk = i - r * 48;
        int row = min(row0 + r, Nn - 1);
        int c = kk & 15, seg = kk >> 4;
        float v = (seg == 0) ? x[row * 16 + c]
                : (seg == 1) ? g_tx1[row * 16 + c]
                             : g_tx2[row * 16 + c];
        sAx[kk][r] = v;
    }
    __syncthreads();

    int g = tid >> 6, co = tid & 63;
    ull acc[16];
#pragma unroll
    for (int r = 0; r < 16; r++) acc[r] = 0ull;

    const float* Wgh = Wh + (g * 192) * 64 + co;
    for (int kk = 0; kk < 192; kk++) {
        float w = Wgh[kk * 64];
        ull w2 = pack2(w, w);
        const ull* ap = (const ull*)sAh[kk];
#pragma unroll
        for (int r = 0; r < 16; r++) ffma2(acc[r], ap[r], w2);
    }
    const float* Wgx = Wx + (g * 48) * 64 + co;
    for (int kk = 0; kk < 48; kk++) {
        float w = Wgx[kk * 64];
        ull w2 = pack2(w, w);
        const ull* ap = (const ull*)sAx[kk];
#pragma unroll
        for (int r = 0; r < 16; r++) ffma2(acc[r], ap[r], w2);
    }

    float b = bh[g * 64 + co] + bx[g * 64 + co];
#pragma unroll
    for (int r = 0; r < 16; r++) {
        float2 v = unpack2(acc[r]);
        int rowa = row0 + 2 * r, rowb = rowa + 1;
        float sa = sigmoid_ap(v.x + b);
        float sb = sigmoid_ap(v.y + b);
        if (g == 0) {
            if (rowa < Nn) g_z[rowa * 64 + co] = sa;
            if (rowb < Nn) g_z[rowb * 64 + co] = sb;
        } else {
            if (rowa < Nn) g_hr[rowa * 64 + co] = sa * h0[rowa * 64 + co];
            if (rowb < Nn) g_hr[rowb * 64 + co] = sb * h0[rowb * 64 + co];
        }
    }
}

// ---------------- GEMM til: -> htil, h (blend), + fused y = relu(h)@Wlin ------
__global__ void k_gemm_til(const float* __restrict__ x,  const float* __restrict__ h0,
                           const float* __restrict__ Wx, const float* __restrict__ Wh,
                           const float* __restrict__ bx, const float* __restrict__ bh,
                           const float* __restrict__ Wlin, const float* __restrict__ blin,
                           float* __restrict__ hout, float* __restrict__ yout) {
    __shared__ __align__(16) float sAh[192][34];
    __shared__ __align__(16) float sAx[48][34];
    __shared__ float sH[GR][65];
    int tid  = threadIdx.x;
    int row0 = blockIdx.x * GR;
    for (int i = tid; i < GR * 192; i += 128) {
        int r = i / 192, kk = i - r * 192;
        int row = min(row0 + r, Nn - 1);
        int c = kk & 63, seg = kk >> 6;
        float v = (seg == 0) ? g_hr[row * 64 + c]
                : (seg == 1) ? g_tr1[row * 64 + c]
                             : g_tr2[row * 64 + c];
        sAh[kk][r] = v;
    }
    for (int i = tid; i < GR * 48; i += 128) {
        int r = i / 48, kk = i - r * 48;
        int row = min(row0 + r, Nn - 1);
        int c = kk & 15, seg = kk >> 4;
        float v = (seg == 0) ? x[row * 16 + c]
                : (seg == 1) ? g_tx1[row * 16 + c]
                             : g_tx2[row * 16 + c];
        sAx[kk][r] = v;
    }
    __syncthreads();

    int co = tid & 63, rh = tid >> 6;
    ull acc[8];
#pragma unroll
    for (int r = 0; r < 8; r++) acc[r] = 0ull;

    const float* Wgh = Wh + (2 * 192) * 64 + co;
    for (int kk = 0; kk < 192; kk++) {
        float w = Wgh[kk * 64];
        ull w2 = pack2(w, w);
        const ull* ap = (const ull*)sAh[kk] + rh * 8;
#pragma unroll
        for (int r = 0; r < 8; r++) ffma2(acc[r], ap[r], w2);
    }
    const float* Wgx = Wx + (2 * 48) * 64 + co;
    for (int kk = 0; kk < 48; kk++) {
        float w = Wgx[kk * 64];
        ull w2 = pack2(w, w);
        const ull* ap = (const ull*)sAx[kk] + rh * 8;
#pragma unroll
        for (int r = 0; r < 8; r++) ffma2(acc[r], ap[r], w2);
    }

    float b = bh[128 + co] + bx[128 + co];
#pragma unroll
    for (int r = 0; r < 8; r++) {
        float2 v = unpack2(acc[r]);
        int lr = rh * 16 + 2 * r;
#pragma unroll
        for (int hh = 0; hh < 2; hh++) {
            float pre = ((hh == 0) ? v.x : v.y) + b;
            int row = row0 + lr + hh;
            float ht = tanh_ap(pre);
            float z, hv = 0.f;
            if (row < Nn) {
                z  = g_z[row * 64 + co];
                hv = z * h0[row * 64 + co] + (1.0f - z) * ht;
                hout[row * 64 + co] = hv;
            }
            sH[lr + hh][co] = fmaxf(hv, 0.f);
        }
    }
    __syncthreads();

    for (int i = tid; i < GR * 7; i += 128) {
        int r = i / 7, j = i - r * 7;
        int row = row0 + r;
        if (row >= Nn) continue;
        float s = blin[j];
#pragma unroll 16
        for (int c = 0; c < 64; c++) s = fmaf(sH[r][c], Wlin[c * 7 + j], s);
        yout[row * 7 + j] = s;
    }
}

// ---------------- launch ------------------------------------------------------
extern "C" void kernel_launch(void* const* d_in, const int* in_sizes, int n_in,
                              void* d_out, int out_size) {
    const float* x    = (const float*)d_in[0];
    const void*  ei   = d_in[1];
    const float* ew   = (const float*)d_in[2];
    const float* h0   = (const float*)d_in[3];
    const float* Wx   = (const float*)d_in[4];
    const float* Wh   = (const float*)d_in[5];
    const float* bx   = (const float*)d_in[6];
    const float* bh   = (const float*)d_in[7];
    const float* Wlin = (const float*)d_in[8];
    const float* blin = (const float*)d_in[9];
    float* out  = (float*)d_out;
    float* hout = out;
    float* yout = out + (size_t)Nn * 64;

    const int TB = 256;
    const int gN = (Nn + TB - 1) / TB;
    const int gE = (Ee + TB - 1) / TB;
    const int gW = (Nn * 32 + TB - 1) / TB;   // warp-per-node grids
    const int gG = (Nn + GR - 1) / GR;        // GEMM grids

    k_init  <<<gN, TB>>>((const unsigned*)ei);
    k_degcnt<<<gE, TB>>>(ei, ew);
    k_scan1 <<<NBLK, SBK>>>();
    k_scan2 <<<1, SBK>>>();
    k_scan3 <<<NBLK, SBK>>>();
    k_csr   <<<gE, TB>>>(ei, ew);

    k_prop_xh1<<<gW, TB>>>(x, h0);
    k_prop_xh2<<<gW, TB>>>(x, h0);
    k_gemm_zr <<<gG, 128>>>(x, h0, Wx, Wh, bx, bh);

    k_prop_r1 <<<gW, TB>>>();
    k_prop_r2 <<<gW, TB>>>();
    k_gemm_til<<<gG, 128>>>(x, h0, Wx, Wh, bx, bh, Wlin, blin, hout, yout);
}